// round 2
// baseline (speedup 1.0000x reference)
#include <cuda_runtime.h>
#include <cuda_bf16.h>

#define N_NODES 50000
#define N_EDGES 800000
#define IN_DIM  64
#define HID_DIM 128
#define OUT_DIM 64

// ---------------- scratch (static device globals; no allocation) ----------------
__device__ __align__(16) float g_hz[N_NODES * HID_DIM];   // z @ W1
__device__ __align__(16) float g_h [N_NODES * HID_DIM];   // relu(aggregated layer 1)
__device__ __align__(16) float g_hw[N_NODES * OUT_DIM];   // h @ W2
__device__ float g_dinv[N_NODES];           // deg^-1/2
__device__ int   g_cnt[N_NODES];            // in-degree counts (excl self-loop)
__device__ int   g_cur[N_NODES];            // scatter cursors
__device__ int   g_rowptr[N_NODES + 1];     // CSR row pointers (by dst)
__device__ int   g_esrc[N_EDGES];           // src ids bucketed by dst
__device__ int   g_blocksums[64];

// ---------------- degree / CSR build ----------------
__global__ void k_cnt0() {
    int i = blockIdx.x * blockDim.x + threadIdx.x;
    if (i < N_NODES) g_cnt[i] = 0;
}

__global__ void k_count(const int* __restrict__ ei) {
    int e = blockIdx.x * blockDim.x + threadIdx.x;
    if (e < N_EDGES) {
        int d = ei[N_EDGES + e];   // dst row (int32)
        atomicAdd(&g_cnt[d], 1);
    }
}

// inclusive scan of g_cnt into g_rowptr[i+1], per 1024-block, block sums out
__global__ void k_scan1() {
    __shared__ int s[1024];
    int i = blockIdx.x * 1024 + threadIdx.x;
    int v = (i < N_NODES) ? g_cnt[i] : 0;
    s[threadIdx.x] = v;
    __syncthreads();
    for (int off = 1; off < 1024; off <<= 1) {
        int t = 0;
        if ((int)threadIdx.x >= off) t = s[threadIdx.x - off];
        __syncthreads();
        s[threadIdx.x] += t;
        __syncthreads();
    }
    if (i < N_NODES) g_rowptr[i + 1] = s[threadIdx.x];
    if (threadIdx.x == 1023) g_blocksums[blockIdx.x] = s[1023];
}

__global__ void k_scan2(int nb) {
    if (threadIdx.x == 0) {
        int acc = 0;
        for (int b = 0; b < nb; b++) {
            int t = g_blocksums[b];
            g_blocksums[b] = acc;
            acc += t;
        }
    }
}

__global__ void k_scan3() {
    int i = blockIdx.x * 1024 + threadIdx.x;
    if (i < N_NODES) g_rowptr[i + 1] += g_blocksums[blockIdx.x];
    if (i == 0) g_rowptr[0] = 0;
}

__global__ void k_dinv_cursor() {
    int i = blockIdx.x * blockDim.x + threadIdx.x;
    if (i < N_NODES) {
        // degree includes self-loop -> always >= 1
        g_dinv[i] = rsqrtf((float)(g_cnt[i] + 1));
        g_cur[i] = g_rowptr[i];
    }
}

__global__ void k_scatter(const int* __restrict__ ei) {
    int e = blockIdx.x * blockDim.x + threadIdx.x;
    if (e < N_EDGES) {
        int s = ei[e];
        int d = ei[N_EDGES + e];
        int pos = atomicAdd(&g_cur[d], 1);
        g_esrc[pos] = s;
    }
}

// ---------------- GEMM 1: hz = z @ W1   [50000,64] x [64,128] ----------------
// warp per node; lane owns 4 output cols (float4); W1 staged in smem.
__global__ void k_gemm1(const float* __restrict__ z, const float* __restrict__ W1) {
    __shared__ float4 sW[IN_DIM * HID_DIM / 4];     // 32 KB
    __shared__ float  sZ[4][IN_DIM];
    int lane = threadIdx.x & 31;
    int w    = threadIdx.x >> 5;
    for (int i = threadIdx.x; i < IN_DIM * HID_DIM / 4; i += 128)
        sW[i] = ((const float4*)W1)[i];
    __syncthreads();

    for (int node = blockIdx.x * 4 + w; node < N_NODES; node += gridDim.x * 4) {
        sZ[w][lane]      = z[node * IN_DIM + lane];
        sZ[w][lane + 32] = z[node * IN_DIM + lane + 32];
        __syncwarp();
        float4 acc = make_float4(0.f, 0.f, 0.f, 0.f);
        #pragma unroll
        for (int k = 0; k < IN_DIM; k++) {
            float  zk = sZ[w][k];
            float4 wv = sW[k * 32 + lane];
            acc.x += zk * wv.x; acc.y += zk * wv.y;
            acc.z += zk * wv.z; acc.w += zk * wv.w;
        }
        ((float4*)g_hz)[node * 32 + lane] = acc;
        __syncwarp();
    }
}

// ---------------- Aggregation 1: h = relu(sum_in hz[src]*norm + self + b1) ----------------
__global__ void k_agg1(const float* __restrict__ b1) {
    int gw   = (blockIdx.x * blockDim.x + threadIdx.x) >> 5;
    int lane = threadIdx.x & 31;
    if (gw >= N_NODES) return;
    int node = gw;
    float di = g_dinv[node];
    float s2 = di * di;
    float4 self = ((const float4*)g_hz)[node * 32 + lane];
    float4 bv   = ((const float4*)b1)[lane];
    float4 acc;
    acc.x = self.x * s2 + bv.x;
    acc.y = self.y * s2 + bv.y;
    acc.z = self.z * s2 + bv.z;
    acc.w = self.w * s2 + bv.w;

    int beg = g_rowptr[node], end = g_rowptr[node + 1];
    #pragma unroll 4
    for (int e = beg; e < end; e++) {
        int   s   = __ldg(&g_esrc[e]);
        float wgt = __ldg(&g_dinv[s]) * di;
        float4 hv = ((const float4*)g_hz)[s * 32 + lane];
        acc.x += wgt * hv.x; acc.y += wgt * hv.y;
        acc.z += wgt * hv.z; acc.w += wgt * hv.w;
    }
    acc.x = fmaxf(acc.x, 0.f); acc.y = fmaxf(acc.y, 0.f);
    acc.z = fmaxf(acc.z, 0.f); acc.w = fmaxf(acc.w, 0.f);
    ((float4*)g_h)[node * 32 + lane] = acc;
}

// ---------------- GEMM 2: hw = h @ W2   [50000,128] x [128,64] ----------------
// warp per node; lane owns 2 output cols (float2); W2 staged in smem.
__global__ void k_gemm2(const float* __restrict__ W2) {
    __shared__ float2 sW[HID_DIM * OUT_DIM / 2];    // 32 KB
    __shared__ float  sZ[4][HID_DIM];
    int lane = threadIdx.x & 31;
    int w    = threadIdx.x >> 5;
    for (int i = threadIdx.x; i < HID_DIM * OUT_DIM / 2; i += 128)
        sW[i] = ((const float2*)W2)[i];
    __syncthreads();

    for (int node = blockIdx.x * 4 + w; node < N_NODES; node += gridDim.x * 4) {
        #pragma unroll
        for (int j = 0; j < 4; j++)
            sZ[w][lane + 32 * j] = g_h[node * HID_DIM + lane + 32 * j];
        __syncwarp();
        float2 acc = make_float2(0.f, 0.f);
        #pragma unroll
        for (int k = 0; k < HID_DIM; k++) {
            float  zk = sZ[w][k];
            float2 wv = sW[k * 32 + lane];
            acc.x += zk * wv.x; acc.y += zk * wv.y;
        }
        ((float2*)g_hw)[node * 32 + lane] = acc;
        __syncwarp();
    }
}

// ---------------- Aggregation 2: out = sum_in hw[src]*norm + self + b2 ----------------
__global__ void k_agg2(const float* __restrict__ b2, float* __restrict__ out) {
    int gw   = (blockIdx.x * blockDim.x + threadIdx.x) >> 5;
    int lane = threadIdx.x & 31;
    if (gw >= N_NODES) return;
    int node = gw;
    float di = g_dinv[node];
    float s2 = di * di;
    float2 self = ((const float2*)g_hw)[node * 32 + lane];
    float2 bv   = ((const float2*)b2)[lane];
    float2 acc;
    acc.x = self.x * s2 + bv.x;
    acc.y = self.y * s2 + bv.y;

    int beg = g_rowptr[node], end = g_rowptr[node + 1];
    #pragma unroll 4
    for (int e = beg; e < end; e++) {
        int   s   = __ldg(&g_esrc[e]);
        float wgt = __ldg(&g_dinv[s]) * di;
        float2 hv = ((const float2*)g_hw)[s * 32 + lane];
        acc.x += wgt * hv.x; acc.y += wgt * hv.y;
    }
    ((float2*)out)[node * 32 + lane] = acc;
}

// ---------------- launch ----------------
extern "C" void kernel_launch(void* const* d_in, const int* in_sizes, int n_in,
                              void* d_out, int out_size) {
    // Bind inputs by element count (robust to metadata ordering):
    //   z: 3,200,000   edge_index: 1,600,000   W1/W2: 8192 (in order)   b1: 128   b2: 64
    const float* z  = nullptr;
    const int*   ei = nullptr;
    const float* W1 = nullptr;
    const float* W2 = nullptr;
    const float* b1 = nullptr;
    const float* b2 = nullptr;
    for (int i = 0; i < n_in; i++) {
        int n = in_sizes[i];
        if      (n == N_NODES * IN_DIM)  z  = (const float*)d_in[i];
        else if (n == 2 * N_EDGES)       ei = (const int*)d_in[i];
        else if (n == IN_DIM * HID_DIM) { if (!W1) W1 = (const float*)d_in[i]; else W2 = (const float*)d_in[i]; }
        else if (n == HID_DIM)           b1 = (const float*)d_in[i];
        else if (n == OUT_DIM)           b2 = (const float*)d_in[i];
    }
    float* out = (float*)d_out;

    const int gN  = (N_NODES + 255) / 256;
    const int gE  = (N_EDGES + 255) / 256;
    const int gSC = (N_NODES + 1023) / 1024;          // 49 scan blocks
    const int gW  = (N_NODES * 32 + 255) / 256;        // warp-per-node grids

    k_cnt0<<<gN, 256>>>();
    k_count<<<gE, 256>>>(ei);
    k_scan1<<<gSC, 1024>>>();
    k_scan2<<<1, 32>>>(gSC);
    k_scan3<<<gSC, 1024>>>();
    k_dinv_cursor<<<gN, 256>>>();
    k_scatter<<<gE, 256>>>(ei);

    k_gemm1<<<1024, 128>>>(z, W1);
    k_agg1<<<gW, 256>>>(b1);
    k_gemm2<<<1024, 128>>>(W2);
    k_agg2<<<gW, 256>>>(b2, out);
}

// round 3
// speedup vs baseline: 1.1453x; 1.1453x over previous
#include <cuda_runtime.h>
#include <cuda_bf16.h>

#define N_NODES 50000
#define N_EDGES 800000
#define IN_DIM  64
#define HID_DIM 128
#define OUT_DIM 64

// ---------------- scratch (static device globals; no allocation) ----------------
__device__ __align__(16) float g_az[N_NODES * IN_DIM];    // A_norm @ z
__device__ __align__(16) float g_h [N_NODES * HID_DIM];   // relu(az @ W1 + b1)
__device__ __align__(16) float g_hw[N_NODES * OUT_DIM];   // h @ W2
__device__ float g_dinv[N_NODES];           // deg^-1/2
__device__ int   g_cnt[N_NODES];            // in-degree counts (excl self-loop)
__device__ int   g_cur[N_NODES];            // scatter cursors
__device__ int   g_rowptr[N_NODES + 1];     // CSR row pointers (by dst)
__device__ int   g_esrc[N_EDGES];           // src ids bucketed by dst
__device__ int   g_blocksums[64];

// ---------------- degree / CSR build ----------------
__global__ void k_cnt0() {
    int i = blockIdx.x * blockDim.x + threadIdx.x;
    if (i < N_NODES) g_cnt[i] = 0;
}

__global__ void k_count(const int* __restrict__ ei) {
    int e = blockIdx.x * blockDim.x + threadIdx.x;
    if (e < N_EDGES) atomicAdd(&g_cnt[ei[N_EDGES + e]], 1);
}

// per-1024-block inclusive scan of g_cnt into g_rowptr[i+1], block sums out
__global__ void k_scan1() {
    __shared__ int s[1024];
    int i = blockIdx.x * 1024 + threadIdx.x;
    int v = (i < N_NODES) ? g_cnt[i] : 0;
    s[threadIdx.x] = v;
    __syncthreads();
    for (int off = 1; off < 1024; off <<= 1) {
        int t = 0;
        if ((int)threadIdx.x >= off) t = s[threadIdx.x - off];
        __syncthreads();
        s[threadIdx.x] += t;
        __syncthreads();
    }
    if (i < N_NODES) g_rowptr[i + 1] = s[threadIdx.x];
    if (threadIdx.x == 1023) g_blocksums[blockIdx.x] = s[1023];
}

// exclusive warp-shfl scan of <=64 block sums (replaces the serial loop)
__global__ void k_scan2(int nb) {
    int lane = threadIdx.x;
    int i0 = 2 * lane, i1 = 2 * lane + 1;
    int a = (i0 < nb) ? g_blocksums[i0] : 0;
    int b = (i1 < nb) ? g_blocksums[i1] : 0;
    int s = a + b;
    #pragma unroll
    for (int off = 1; off < 32; off <<= 1) {
        int t = __shfl_up_sync(0xffffffff, s, off);
        if (lane >= off) s += t;
    }
    int excl = s - (a + b);
    if (i0 < nb) g_blocksums[i0] = excl;
    if (i1 < nb) g_blocksums[i1] = excl + a;
}

// finalize rowptr + compute dinv + init cursors (fused)
__global__ void k_scan3() {
    int i = blockIdx.x * 1024 + threadIdx.x;
    if (i < N_NODES) {
        int cnt = g_cnt[i];
        int end = g_rowptr[i + 1] + g_blocksums[blockIdx.x];
        g_rowptr[i + 1] = end;
        g_cur[i] = end - cnt;                       // == rowptr[i]
        g_dinv[i] = rsqrtf((float)(cnt + 1));       // self-loop included
    }
    if (i == 0) g_rowptr[0] = 0;
}

__global__ void k_scatter(const int* __restrict__ ei) {
    int e = blockIdx.x * blockDim.x + threadIdx.x;
    if (e < N_EDGES) {
        int s = ei[e];
        int d = ei[N_EDGES + e];
        int pos = atomicAdd(&g_cur[d], 1);
        g_esrc[pos] = s;
    }
}

// ---------------- Aggregation 0: az = A_norm @ z   (64-dim, float2/lane) ----------------
__global__ __launch_bounds__(256) void k_aggz(const float* __restrict__ z) {
    int gw   = (blockIdx.x * blockDim.x + threadIdx.x) >> 5;
    int lane = threadIdx.x & 31;
    if (gw >= N_NODES) return;
    float di = g_dinv[gw];
    float s2 = di * di;
    float2 self = ((const float2*)z)[gw * 32 + lane];
    float2 acc = make_float2(self.x * s2, self.y * s2);

    int beg = g_rowptr[gw], end = g_rowptr[gw + 1];
    int e = beg;
    for (; e + 4 <= end; e += 4) {
        int i0 = __ldg(&g_esrc[e]);
        int i1 = __ldg(&g_esrc[e + 1]);
        int i2 = __ldg(&g_esrc[e + 2]);
        int i3 = __ldg(&g_esrc[e + 3]);
        float w0 = __ldg(&g_dinv[i0]) * di;
        float w1 = __ldg(&g_dinv[i1]) * di;
        float w2 = __ldg(&g_dinv[i2]) * di;
        float w3 = __ldg(&g_dinv[i3]) * di;
        float2 v0 = ((const float2*)z)[i0 * 32 + lane];
        float2 v1 = ((const float2*)z)[i1 * 32 + lane];
        float2 v2 = ((const float2*)z)[i2 * 32 + lane];
        float2 v3 = ((const float2*)z)[i3 * 32 + lane];
        acc.x += w0 * v0.x; acc.y += w0 * v0.y;
        acc.x += w1 * v1.x; acc.y += w1 * v1.y;
        acc.x += w2 * v2.x; acc.y += w2 * v2.y;
        acc.x += w3 * v3.x; acc.y += w3 * v3.y;
    }
    for (; e < end; e++) {
        int   s   = __ldg(&g_esrc[e]);
        float wgt = __ldg(&g_dinv[s]) * di;
        float2 v  = ((const float2*)z)[s * 32 + lane];
        acc.x += wgt * v.x; acc.y += wgt * v.y;
    }
    ((float2*)g_az)[gw * 32 + lane] = acc;
}

// ---------------- GEMM 1 (fused bias+relu): h = relu(az @ W1 + b1) ----------------
__global__ __launch_bounds__(128) void k_gemm1(const float* __restrict__ W1,
                                               const float* __restrict__ b1) {
    __shared__ float4 sW[IN_DIM * HID_DIM / 4];     // 32 KB
    __shared__ float  sX[4][IN_DIM];
    int lane = threadIdx.x & 31;
    int w    = threadIdx.x >> 5;
    for (int i = threadIdx.x; i < IN_DIM * HID_DIM / 4; i += 128)
        sW[i] = ((const float4*)W1)[i];
    __syncthreads();
    float4 bv = ((const float4*)b1)[lane];

    for (int node = blockIdx.x * 4 + w; node < N_NODES; node += gridDim.x * 4) {
        sX[w][lane]      = g_az[node * IN_DIM + lane];
        sX[w][lane + 32] = g_az[node * IN_DIM + lane + 32];
        __syncwarp();
        float4 acc = bv;
        #pragma unroll
        for (int k = 0; k < IN_DIM; k++) {
            float  xk = sX[w][k];
            float4 wv = sW[k * 32 + lane];
            acc.x += xk * wv.x; acc.y += xk * wv.y;
            acc.z += xk * wv.z; acc.w += xk * wv.w;
        }
        acc.x = fmaxf(acc.x, 0.f); acc.y = fmaxf(acc.y, 0.f);
        acc.z = fmaxf(acc.z, 0.f); acc.w = fmaxf(acc.w, 0.f);
        ((float4*)g_h)[node * 32 + lane] = acc;
        __syncwarp();
    }
}

// ---------------- GEMM 2: hw = h @ W2   [50000,128] x [128,64] ----------------
__global__ __launch_bounds__(128) void k_gemm2(const float* __restrict__ W2) {
    __shared__ float2 sW[HID_DIM * OUT_DIM / 2];    // 32 KB
    __shared__ float  sX[4][HID_DIM];
    int lane = threadIdx.x & 31;
    int w    = threadIdx.x >> 5;
    for (int i = threadIdx.x; i < HID_DIM * OUT_DIM / 2; i += 128)
        sW[i] = ((const float2*)W2)[i];
    __syncthreads();

    for (int node = blockIdx.x * 4 + w; node < N_NODES; node += gridDim.x * 4) {
        #pragma unroll
        for (int j = 0; j < 4; j++)
            sX[w][lane + 32 * j] = g_h[node * HID_DIM + lane + 32 * j];
        __syncwarp();
        float2 acc = make_float2(0.f, 0.f);
        #pragma unroll
        for (int k = 0; k < HID_DIM; k++) {
            float  xk = sX[w][k];
            float2 wv = sW[k * 32 + lane];
            acc.x += xk * wv.x; acc.y += xk * wv.y;
        }
        ((float2*)g_hw)[node * 32 + lane] = acc;
        __syncwarp();
    }
}

// ---------------- Aggregation 2: out = A_norm @ hw + b2 ----------------
__global__ __launch_bounds__(256) void k_agg2(const float* __restrict__ b2,
                                              float* __restrict__ out) {
    int gw   = (blockIdx.x * blockDim.x + threadIdx.x) >> 5;
    int lane = threadIdx.x & 31;
    if (gw >= N_NODES) return;
    float di = g_dinv[gw];
    float s2 = di * di;
    float2 self = ((const float2*)g_hw)[gw * 32 + lane];
    float2 bv   = ((const float2*)b2)[lane];
    float2 acc;
    acc.x = self.x * s2 + bv.x;
    acc.y = self.y * s2 + bv.y;

    int beg = g_rowptr[gw], end = g_rowptr[gw + 1];
    int e = beg;
    for (; e + 4 <= end; e += 4) {
        int i0 = __ldg(&g_esrc[e]);
        int i1 = __ldg(&g_esrc[e + 1]);
        int i2 = __ldg(&g_esrc[e + 2]);
        int i3 = __ldg(&g_esrc[e + 3]);
        float w0 = __ldg(&g_dinv[i0]) * di;
        float w1 = __ldg(&g_dinv[i1]) * di;
        float w2 = __ldg(&g_dinv[i2]) * di;
        float w3 = __ldg(&g_dinv[i3]) * di;
        float2 v0 = ((const float2*)g_hw)[i0 * 32 + lane];
        float2 v1 = ((const float2*)g_hw)[i1 * 32 + lane];
        float2 v2 = ((const float2*)g_hw)[i2 * 32 + lane];
        float2 v3 = ((const float2*)g_hw)[i3 * 32 + lane];
        acc.x += w0 * v0.x; acc.y += w0 * v0.y;
        acc.x += w1 * v1.x; acc.y += w1 * v1.y;
        acc.x += w2 * v2.x; acc.y += w2 * v2.y;
        acc.x += w3 * v3.x; acc.y += w3 * v3.y;
    }
    for (; e < end; e++) {
        int   s   = __ldg(&g_esrc[e]);
        float wgt = __ldg(&g_dinv[s]) * di;
        float2 v  = ((const float2*)g_hw)[s * 32 + lane];
        acc.x += wgt * v.x; acc.y += wgt * v.y;
    }
    ((float2*)out)[gw * 32 + lane] = acc;
}

// ---------------- launch ----------------
extern "C" void kernel_launch(void* const* d_in, const int* in_sizes, int n_in,
                              void* d_out, int out_size) {
    const float* z  = nullptr;
    const int*   ei = nullptr;
    const float* W1 = nullptr;
    const float* W2 = nullptr;
    const float* b1 = nullptr;
    const float* b2 = nullptr;
    for (int i = 0; i < n_in; i++) {
        int n = in_sizes[i];
        if      (n == N_NODES * IN_DIM)  z  = (const float*)d_in[i];
        else if (n == 2 * N_EDGES)       ei = (const int*)d_in[i];
        else if (n == IN_DIM * HID_DIM) { if (!W1) W1 = (const float*)d_in[i]; else W2 = (const float*)d_in[i]; }
        else if (n == HID_DIM)           b1 = (const float*)d_in[i];
        else if (n == OUT_DIM)           b2 = (const float*)d_in[i];
    }
    float* out = (float*)d_out;

    const int gN  = (N_NODES + 255) / 256;
    const int gE  = (N_EDGES + 255) / 256;
    const int gSC = (N_NODES + 1023) / 1024;           // 49 scan blocks
    const int gW  = (N_NODES * 32 + 255) / 256;         // warp-per-node grids

    k_cnt0<<<gN, 256>>>();
    k_count<<<gE, 256>>>(ei);
    k_scan1<<<gSC, 1024>>>();
    k_scan2<<<1, 32>>>(gSC);
    k_scan3<<<gSC, 1024>>>();
    k_scatter<<<gE, 256>>>(ei);

    k_aggz <<<gW, 256>>>(z);
    k_gemm1<<<1024, 128>>>(W1, b1);
    k_gemm2<<<1024, 128>>>(W2);
    k_agg2 <<<gW, 256>>>(b2, out);
}